// round 5
// baseline (speedup 1.0000x reference)
#include <cuda_runtime.h>
#include <math.h>

// ---------------------------------------------------------------------------
// Problem constants
// ---------------------------------------------------------------------------
static constexpr int NN = 50000;    // nodes
static constexpr int NE = 800000;   // edges
static constexpr int F1 = 128;      // in_feats
static constexpr int HF = 256;      // h_feats
static constexpr int CF = 32;       // classes

// ---------------------------------------------------------------------------
// Scratch (device globals -- no allocation allowed)
// ---------------------------------------------------------------------------
__device__ __align__(16) float g_w1 [(size_t)NE * F1];      // 409.6 MB: layer-1 edge weights (kept for layer 2)
__device__ __align__(16) float g_bufA[(size_t)NE * HF];     // 819.2 MB
__device__ __align__(16) float g_bufB[(size_t)NE * HF];     // 819.2 MB
__device__ __align__(16) float g_h1 [(size_t)NN * HF];      // layer-1 output h (relu'd)
__device__ __align__(16) float g_hN [(size_t)NN * HF];      // neighbor-sum accumulator
__device__ __align__(16) float g_cat[(size_t)NN * 2 * HF];  // concat(h, h_N/deg)
__device__ float g_inv[NN];                                  // per-node 1/max(||h||, eps)
__device__ int   g_deg[NN];                                  // in-degree (dst counts)

// ---------------------------------------------------------------------------
// GEMM: C = act_out( act_in(A) @ B + bias )
// A [M,K] row-major, B [K,N] row-major, bias [N].
// 128x128 tile, BK=16, 256 threads, 8x8 per thread, packed fma.rn.f32x2 inner.
// K must be a multiple of 16 and N a multiple of 4 (holds for all calls).
// ---------------------------------------------------------------------------
template<bool RELU_IN, bool RELU_OUT>
__launch_bounds__(256)
__global__ void gemm_bias_kernel(const float* __restrict__ A,
                                 const float* __restrict__ B,
                                 const float* __restrict__ bias,
                                 float* __restrict__ C,
                                 int M, int N, int K)
{
    __shared__ float As[16][128];   // transposed A tile: As[k][m]
    __shared__ float Bs[16][128];   // Bs[k][n]

    const int tid = threadIdx.x;
    const int tx  = tid & 15;       // output col group (8 cols)
    const int ty  = tid >> 4;       // output row group (8 rows)
    const int m0  = blockIdx.y * 128;
    const int n0  = blockIdx.x * 128;

    unsigned long long acc[8][4];   // 8 rows x 4 f32x2 pairs (8 cols)
    #pragma unroll
    for (int i = 0; i < 8; i++)
        #pragma unroll
        for (int j = 0; j < 4; j++) acc[i][j] = 0ull;

    for (int k0 = 0; k0 < K; k0 += 16) {
        // ---- load A tile (128x16), transpose into As ----
        #pragma unroll
        for (int t = 0; t < 2; t++) {
            int idx = tid + t * 256;
            int ar  = idx >> 2;            // 0..127
            int ac  = (idx & 3) << 2;      // 0,4,8,12
            float4 v = make_float4(0.f, 0.f, 0.f, 0.f);
            int gm = m0 + ar;
            if (gm < M)
                v = *reinterpret_cast<const float4*>(A + (size_t)gm * K + k0 + ac);
            if (RELU_IN) {
                v.x = fmaxf(v.x, 0.f); v.y = fmaxf(v.y, 0.f);
                v.z = fmaxf(v.z, 0.f); v.w = fmaxf(v.w, 0.f);
            }
            As[ac + 0][ar] = v.x; As[ac + 1][ar] = v.y;
            As[ac + 2][ar] = v.z; As[ac + 3][ar] = v.w;
        }
        // ---- load B tile (16x128) ----
        #pragma unroll
        for (int t = 0; t < 2; t++) {
            int idx = tid + t * 256;
            int br  = idx >> 5;            // 0..15
            int bc  = (idx & 31) << 2;     // 0..124
            float4 v = make_float4(0.f, 0.f, 0.f, 0.f);
            if (n0 + bc < N)
                v = *reinterpret_cast<const float4*>(B + (size_t)(k0 + br) * N + n0 + bc);
            *reinterpret_cast<float4*>(&Bs[br][bc]) = v;
        }
        __syncthreads();

        #pragma unroll
        for (int kk = 0; kk < 16; kk++) {
            unsigned long long av[8], bv[4];
            #pragma unroll
            for (int i = 0; i < 8; i++) {
                float a = As[kk][ty * 8 + i];
                asm("mov.b64 %0, {%1, %1};" : "=l"(av[i]) : "f"(a));
            }
            #pragma unroll
            for (int j = 0; j < 4; j++)
                bv[j] = *reinterpret_cast<const unsigned long long*>(&Bs[kk][tx * 8 + 2 * j]);
            #pragma unroll
            for (int i = 0; i < 8; i++)
                #pragma unroll
                for (int j = 0; j < 4; j++)
                    asm("fma.rn.f32x2 %0, %1, %2, %0;"
                        : "+l"(acc[i][j]) : "l"(av[i]), "l"(bv[j]));
        }
        __syncthreads();
    }

    // ---- epilogue: bias (+relu), guarded float4 stores ----
    #pragma unroll
    for (int i = 0; i < 8; i++) {
        int gm = m0 + ty * 8 + i;
        if (gm >= M) continue;
        #pragma unroll
        for (int j = 0; j < 4; j += 2) {
            int gn = n0 + tx * 8 + j * 2;
            if (gn < N) {
                float l0, h0, l1, h1;
                asm("mov.b64 {%0, %1}, %2;" : "=f"(l0), "=f"(h0) : "l"(acc[i][j]));
                asm("mov.b64 {%0, %1}, %2;" : "=f"(l1), "=f"(h1) : "l"(acc[i][j + 1]));
                float4 o;
                o.x = l0 + bias[gn + 0];
                o.y = h0 + bias[gn + 1];
                o.z = l1 + bias[gn + 2];
                o.w = h1 + bias[gn + 3];
                if (RELU_OUT) {
                    o.x = fmaxf(o.x, 0.f); o.y = fmaxf(o.y, 0.f);
                    o.z = fmaxf(o.z, 0.f); o.w = fmaxf(o.w, 0.f);
                }
                *reinterpret_cast<float4*>(C + (size_t)gm * N + gn) = o;
            }
        }
    }
}

// ---------------------------------------------------------------------------
// w1 = edge_feat @ We1 + be1     (E_IN=2, so just 2 FMAs per output element)
// ---------------------------------------------------------------------------
__global__ void w1_kernel(const float* __restrict__ ef, const float* __restrict__ We,
                          const float* __restrict__ be, float* __restrict__ w1)
{
    const int idx = blockIdx.x * 256 + threadIdx.x;   // over NE*F1 exactly
    const int e = idx >> 7;
    const int j = idx & 127;
    const float e0 = ef[2 * e];
    const float e1 = ef[2 * e + 1];
    w1[idx] = fmaf(e1, We[128 + j], fmaf(e0, We[j], be[j]));
}

// ---------------------------------------------------------------------------
// per-node inverse norm: inv[n] = 1 / max(||h[n]||, 1e-12)   (warp per node)
// ---------------------------------------------------------------------------
template<int F>
__global__ void norm_kernel(const float* __restrict__ h, float* __restrict__ invn,
                            int n_nodes)
{
    const int n = blockIdx.x * 8 + (threadIdx.x >> 5);
    if (n >= n_nodes) return;
    const int lane = threadIdx.x & 31;
    const float4* h4 = reinterpret_cast<const float4*>(h + (size_t)n * F);
    float ss = 0.f;
    #pragma unroll
    for (int j = 0; j < F / 128; j++) {
        float4 v = h4[lane + j * 32];
        ss += v.x * v.x + v.y * v.y + v.z * v.z + v.w * v.w;
    }
    #pragma unroll
    for (int o = 16; o > 0; o >>= 1) ss += __shfl_xor_sync(0xFFFFFFFFu, ss, o);
    if (lane == 0) invn[n] = 1.f / fmaxf(sqrtf(ss), 1e-12f);
}

// ---------------------------------------------------------------------------
// per-edge message: m[e,:] = cos_e * w[e,:] * h[src[e],:]
// cos_e = (h[s].h[d]) * inv[s] * inv[d].   Warp per edge. w/m may alias.
// ---------------------------------------------------------------------------
template<int F>
__global__ void msg_kernel(const float* __restrict__ h,
                           const float* w, float* m,
                           const float* __restrict__ invn,
                           const int* __restrict__ src,
                           const int* __restrict__ dst)
{
    const int e    = blockIdx.x * 8 + (threadIdx.x >> 5);
    const int lane = threadIdx.x & 31;
    const int s = src[e];
    const int d = dst[e];
    const float4* hs4 = reinterpret_cast<const float4*>(h + (size_t)s * F);
    const float4* hd4 = reinterpret_cast<const float4*>(h + (size_t)d * F);
    float4 a[F / 128];
    float dot = 0.f;
    #pragma unroll
    for (int j = 0; j < F / 128; j++) {
        a[j] = hs4[lane + j * 32];
        float4 b = hd4[lane + j * 32];
        dot += a[j].x * b.x + a[j].y * b.y + a[j].z * b.z + a[j].w * b.w;
    }
    #pragma unroll
    for (int o = 16; o > 0; o >>= 1) dot += __shfl_xor_sync(0xFFFFFFFFu, dot, o);
    const float c = dot * invn[s] * invn[d];
    const float4* w4 = reinterpret_cast<const float4*>(w + (size_t)e * F);
    float4*       m4 = reinterpret_cast<float4*>(m + (size_t)e * F);
    #pragma unroll
    for (int j = 0; j < F / 128; j++) {
        float4 wv = w4[lane + j * 32];
        float4 o;
        o.x = c * wv.x * a[j].x;
        o.y = c * wv.y * a[j].y;
        o.z = c * wv.z * a[j].z;
        o.w = c * wv.w * a[j].w;
        m4[lane + j * 32] = o;
    }
}

// ---------------------------------------------------------------------------
// degree + scatter-sum
// ---------------------------------------------------------------------------
__global__ void deg_kernel(const int* __restrict__ dst, int* __restrict__ deg)
{
    const int e = blockIdx.x * 256 + threadIdx.x;
    if (e < NE) atomicAdd(&deg[dst[e]], 1);
}

template<int F>
__global__ void scatter_kernel(const float* __restrict__ r,
                               const int* __restrict__ dst,
                               float* hN)
{
    const int e    = blockIdx.x * 8 + (threadIdx.x >> 5);
    const int lane = threadIdx.x & 31;
    const int d = dst[e];
    const float* rr = r + (size_t)e * F;
    float* out = hN + (size_t)d * F;
    #pragma unroll
    for (int j = 0; j < F / 32; j++)
        atomicAdd(out + lane + j * 32, rr[lane + j * 32]);
}

// ---------------------------------------------------------------------------
// cat[n, 0:F] = h[n,:]; cat[n, F:2F] = hN_sum[n,:] / max(deg[n], 1)
// ---------------------------------------------------------------------------
template<int F>
__global__ void cat_kernel(const float* __restrict__ h,
                           const float* __restrict__ hN,
                           const int* __restrict__ deg,
                           float* __restrict__ out, int n_nodes)
{
    const int idx = blockIdx.x * 256 + threadIdx.x;
    if (idx >= n_nodes * 2 * F) return;
    const int n = idx / (2 * F);
    const int k = idx - n * 2 * F;
    float v;
    if (k < F) v = h[(size_t)n * F + k];
    else       v = hN[(size_t)n * F + (k - F)] / fmaxf((float)deg[n], 1.f);
    out[idx] = v;
}

// ---------------------------------------------------------------------------
// launch
// ---------------------------------------------------------------------------
extern "C" void kernel_launch(void* const* d_in, const int* in_sizes, int n_in,
                              void* d_out, int out_size)
{
    (void)in_sizes; (void)n_in; (void)out_size;

    const float* nf   = (const float*)d_in[0];
    const float* ef   = (const float*)d_in[1];
    const int*   src  = (const int*)  d_in[2];
    const int*   dst  = (const int*)  d_in[3];
    const float* We1  = (const float*)d_in[4];
    const float* be1  = (const float*)d_in[5];
    const float* Wr1a = (const float*)d_in[6];
    const float* br1a = (const float*)d_in[7];
    const float* Wr1b = (const float*)d_in[8];
    const float* br1b = (const float*)d_in[9];
    const float* Wl1  = (const float*)d_in[10];
    const float* bl1  = (const float*)d_in[11];
    const float* We2  = (const float*)d_in[12];
    const float* be2  = (const float*)d_in[13];
    const float* Wr2a = (const float*)d_in[14];
    const float* br2a = (const float*)d_in[15];
    const float* Wr2b = (const float*)d_in[16];
    const float* br2b = (const float*)d_in[17];
    const float* Wl2  = (const float*)d_in[18];
    const float* bl2  = (const float*)d_in[19];
    float* out = (float*)d_out;

    float *p_w1, *p_A, *p_B, *p_h1, *p_hN, *p_cat, *p_inv;
    int*   p_deg;
    cudaGetSymbolAddress((void**)&p_w1,  g_w1);
    cudaGetSymbolAddress((void**)&p_A,   g_bufA);
    cudaGetSymbolAddress((void**)&p_B,   g_bufB);
    cudaGetSymbolAddress((void**)&p_h1,  g_h1);
    cudaGetSymbolAddress((void**)&p_hN,  g_hN);
    cudaGetSymbolAddress((void**)&p_cat, g_cat);
    cudaGetSymbolAddress((void**)&p_inv, g_inv);
    cudaGetSymbolAddress((void**)&p_deg, g_deg);

    // degree (shared by both layers)
    cudaMemsetAsync(p_deg, 0, NN * sizeof(int));
    deg_kernel<<<(NE + 255) / 256, 256>>>(dst, p_deg);

    // ======================= layer 1 =======================
    w1_kernel<<<(NE * F1) / 256, 256>>>(ef, We1, be1, p_w1);
    norm_kernel<F1><<<(NN + 7) / 8, 256>>>(nf, p_inv, NN);
    msg_kernel<F1><<<NE / 8, 256>>>(nf, p_w1, p_A, p_inv, src, dst);
    {
        dim3 g(F1 / 128, (NE + 127) / 128);
        gemm_bias_kernel<false, true><<<g, 256>>>(p_A, Wr1a, br1a, p_B, NE, F1, F1);
        gemm_bias_kernel<false, true><<<g, 256>>>(p_B, Wr1b, br1b, p_A, NE, F1, F1);
    }
    cudaMemsetAsync(p_hN, 0, (size_t)NN * F1 * sizeof(float));
    scatter_kernel<F1><<<NE / 8, 256>>>(p_A, dst, p_hN);
    cat_kernel<F1><<<(NN * 2 * F1 + 255) / 256, 256>>>(nf, p_hN, p_deg, p_cat, NN);
    {
        dim3 g(HF / 128, (NN + 127) / 128);
        gemm_bias_kernel<false, true><<<g, 256>>>(p_cat, Wl1, bl1, p_h1, NN, HF, 2 * F1);
    }

    // ======================= layer 2 =======================
    // w2 = relu(w1) @ We2 + be2   (relu fused into A load)
    {
        dim3 g(HF / 128, (NE + 127) / 128);
        gemm_bias_kernel<true, false><<<g, 256>>>(p_w1, We2, be2, p_A, NE, HF, F1);
    }
    norm_kernel<HF><<<(NN + 7) / 8, 256>>>(p_h1, p_inv, NN);
    msg_kernel<HF><<<NE / 8, 256>>>(p_h1, p_A, p_A, p_inv, src, dst);   // in-place
    {
        dim3 g(HF / 128, (NE + 127) / 128);
        gemm_bias_kernel<false, true><<<g, 256>>>(p_A, Wr2a, br2a, p_B, NE, HF, HF);
        gemm_bias_kernel<false, true><<<g, 256>>>(p_B, Wr2b, br2b, p_A, NE, HF, HF);
    }
    cudaMemsetAsync(p_hN, 0, (size_t)NN * HF * sizeof(float));
    scatter_kernel<HF><<<NE / 8, 256>>>(p_A, dst, p_hN);
    cat_kernel<HF><<<(NN * 2 * HF + 255) / 256, 256>>>(p_h1, p_hN, p_deg, p_cat, NN);
    {
        dim3 g(1, (NN + 127) / 128);
        gemm_bias_kernel<false, false><<<g, 256>>>(p_cat, Wl2, bl2, out, NN, CF, 2 * HF);
    }
}

// round 9
// speedup vs baseline: 1.5576x; 1.5576x over previous
#include <cuda_runtime.h>
#include <cuda_bf16.h>
#include <math.h>
#include <stdint.h>

// ---------------------------------------------------------------------------
// Problem constants
// ---------------------------------------------------------------------------
static constexpr int NN = 50000;    // nodes
static constexpr int NE = 800000;   // edges
static constexpr int F1 = 128;      // in_feats
static constexpr int HF = 256;      // h_feats
static constexpr int CF = 32;       // classes

// ---------------------------------------------------------------------------
// Scratch (device globals -- no allocation allowed)
// ---------------------------------------------------------------------------
__device__ __align__(16) float g_w1 [(size_t)NE * F1];      // layer-1 edge weights (kept for layer 2)
__device__ __align__(16) float g_bufA[(size_t)NE * HF];
__device__ __align__(16) float g_bufB[(size_t)NE * HF];
__device__ __align__(16) float g_h1 [(size_t)NN * HF];
__device__ __align__(16) float g_hN [(size_t)NN * HF];
__device__ __align__(16) float g_cat[(size_t)NN * 2 * HF];
__device__ float g_inv[NN];
__device__ int   g_deg[NN];

// split-bf16 weights, pre-transposed to [N, K] K-major
// offsets (elements): Wr1a=0(16384) Wr1b=16384 We2=32768(32768)
//                     Wr2a=65536(65536) Wr2b=131072 Wl1=196608(65536) Wl2=262144(16384)
static constexpr size_t WT_TOTAL = 278528;
__device__ __align__(16) __nv_bfloat16 g_bwh[WT_TOTAL];
__device__ __align__(16) __nv_bfloat16 g_bwl[WT_TOTAL];

// ---------------------------------------------------------------------------
// helpers
// ---------------------------------------------------------------------------
__device__ __forceinline__ uint32_t smem_u32(const void* p) {
    uint32_t a;
    asm("{ .reg .u64 t; cvta.to.shared.u64 t, %1; cvt.u32.u64 %0, t; }" : "=r"(a) : "l"(p));
    return a;
}

__device__ __forceinline__ void ldm4(uint32_t& r0, uint32_t& r1, uint32_t& r2, uint32_t& r3,
                                     uint32_t addr) {
    asm volatile("ldmatrix.sync.aligned.m8n8.x4.shared.b16 {%0,%1,%2,%3}, [%4];"
                 : "=r"(r0), "=r"(r1), "=r"(r2), "=r"(r3) : "r"(addr));
}

__device__ __forceinline__ void mma16816(float* c, const uint32_t* a, const uint32_t* b) {
    asm volatile("mma.sync.aligned.m16n8k16.row.col.f32.bf16.bf16.f32 "
                 "{%0,%1,%2,%3}, {%4,%5,%6,%7}, {%8,%9}, {%0,%1,%2,%3};"
                 : "+f"(c[0]), "+f"(c[1]), "+f"(c[2]), "+f"(c[3])
                 : "r"(a[0]), "r"(a[1]), "r"(a[2]), "r"(a[3]), "r"(b[0]), "r"(b[1]));
}

// split one fp32 pair into packed bf16 hi + bf16 lo (exact residual then rounded)
__device__ __forceinline__ uint32_t split2(float a, float b, uint32_t& lo) {
    __nv_bfloat16 ha = __float2bfloat16(a), hb = __float2bfloat16(b);
    float ra = a - __bfloat162float(ha);
    float rb = b - __bfloat162float(hb);
    __nv_bfloat16 la = __float2bfloat16(ra), lb = __float2bfloat16(rb);
    lo = (uint32_t)__bfloat16_as_ushort(la) | ((uint32_t)__bfloat16_as_ushort(lb) << 16);
    return (uint32_t)__bfloat16_as_ushort(ha) | ((uint32_t)__bfloat16_as_ushort(hb) << 16);
}

// ---------------------------------------------------------------------------
// Weight pre-transform: W[K,N] fp32 -> Bt_hi/Bt_lo [N,K] bf16
// ---------------------------------------------------------------------------
__global__ void conv_w_kernel(const float* __restrict__ W, int K, int N,
                              __nv_bfloat16* __restrict__ hi, __nv_bfloat16* __restrict__ lo)
{
    const int idx = blockIdx.x * 256 + threadIdx.x;
    if (idx >= K * N) return;
    const int k = idx / N;
    const int n = idx - k * N;
    const float x = W[idx];
    const __nv_bfloat16 h = __float2bfloat16(x);
    const float r = x - __bfloat162float(h);
    hi[(size_t)n * K + k] = h;
    lo[(size_t)n * K + k] = __float2bfloat16(r);
}

// ---------------------------------------------------------------------------
// bf16 split-3 GEMM via mma.sync.m16n8k16 (legacy HMMA path, compute_103-safe)
// C[M,N] = act_out( act_in(A[M,K]) @ B[K,N] + bias )
// B pre-split/transposed to [N,K] bf16 hi/lo.
// CTA tile: 128(M) x CTA_N.  grid = (ceil(M/128), N/CTA_N).
// 8 warps: 4 along M (32 rows each) x 2 along N (CTA_N/2 each).
// K streamed in 64-col chunks: A fp32 -> split bf16 hi/lo in SMEM.
// SMEM rows padded to 144B => conflict-free ldmatrix.
// ---------------------------------------------------------------------------
template<int CTA_N, bool RELU_IN, bool RELU_OUT>
__launch_bounds__(256, 2)
__global__ void gemm_mma(const float* __restrict__ A,
                         const __nv_bfloat16* __restrict__ Bh,
                         const __nv_bfloat16* __restrict__ Bl,
                         const float* __restrict__ bias,
                         float* __restrict__ C,
                         int M, int K, int N)
{
    extern __shared__ char sm[];
    constexpr int RS    = 144;                 // SMEM row stride bytes (64 bf16 + pad)
    constexpr int S_AHI = 0;
    constexpr int S_ALO = 128 * RS;            // 18432
    constexpr int S_BHI = 2 * 128 * RS;        // 36864
    constexpr int S_BLO = S_BHI + CTA_N * RS;
    constexpr int SPAN  = CTA_N / 2;           // per-warp N span
    constexpr int NI    = SPAN / 8;            // n-tiles per warp

    const int tid    = threadIdx.x;
    const int lane   = tid & 31;
    const int warp   = tid >> 5;
    const int warp_m = warp & 3;
    const int warp_n = warp >> 2;
    const int m0     = blockIdx.x * 128;
    const int n0     = blockIdx.y * CTA_N;

    const uint32_t sb = smem_u32(sm);
    // ldmatrix lane offset: rows (lane&7)+8*((lane>>3)&1), col-group (lane>>4)*8 elems
    const uint32_t lmo = ((lane & 7) + ((lane >> 3) & 1) * 8) * RS + (lane >> 4) * 16;
    const uint32_t a_base = sb + S_AHI + (uint32_t)(warp_m * 32) * RS + lmo;
    const uint32_t b_base = sb + S_BHI + (uint32_t)(warp_n * SPAN) * RS + lmo;

    float acc[2][NI][4];
    #pragma unroll
    for (int mi = 0; mi < 2; mi++)
        #pragma unroll
        for (int ni = 0; ni < NI; ni++)
            #pragma unroll
            for (int c = 0; c < 4; c++) acc[mi][ni][c] = 0.f;

    const int NC = K >> 6;
    for (int kc = 0; kc < NC; kc++) {
        // ---- A chunk: 128 rows x 64 fp32 -> split bf16 hi/lo ----
        #pragma unroll
        for (int i = 0; i < 8; i++) {
            const int slot = tid + i * 256;        // 0..2047 (float4 slots)
            const int row  = slot >> 4;
            const int c4   = slot & 15;
            const int gm   = m0 + row;
            float4 v = make_float4(0.f, 0.f, 0.f, 0.f);
            if (gm < M)
                v = *reinterpret_cast<const float4*>(A + (size_t)gm * K + kc * 64 + c4 * 4);
            if (RELU_IN) {
                v.x = fmaxf(v.x, 0.f); v.y = fmaxf(v.y, 0.f);
                v.z = fmaxf(v.z, 0.f); v.w = fmaxf(v.w, 0.f);
            }
            uint32_t l0, l1;
            const uint32_t h0 = split2(v.x, v.y, l0);
            const uint32_t h1 = split2(v.z, v.w, l1);
            const int off = row * RS + c4 * 8;
            *reinterpret_cast<uint2*>(sm + S_AHI + off) = make_uint2(h0, h1);
            *reinterpret_cast<uint2*>(sm + S_ALO + off) = make_uint2(l0, l1);
        }
        // ---- B chunk: CTA_N rows x 64 bf16 (hi & lo) ----
        #pragma unroll
        for (int i = 0; i < CTA_N / 32; i++) {
            const int slot = tid + i * 256;        // 0..CTA_N*8-1 (uint4 slots)
            const int n    = slot >> 3;
            const int grp  = slot & 7;
            const size_t go = (size_t)(n0 + n) * K + kc * 64 + grp * 8;
            const uint4 vh = *reinterpret_cast<const uint4*>(Bh + go);
            const uint4 vl = *reinterpret_cast<const uint4*>(Bl + go);
            const int off = n * RS + grp * 16;
            *reinterpret_cast<uint4*>(sm + S_BHI + off) = vh;
            *reinterpret_cast<uint4*>(sm + S_BLO + off) = vl;
        }
        __syncthreads();

        // ---- 3 split terms: (Ahi,Bhi), (Ahi,Blo), (Alo,Bhi) ----
        #pragma unroll
        for (int s = 0; s < 3; s++) {
            const uint32_t ab = a_base + ((s == 2) ? (uint32_t)(S_ALO - S_AHI) : 0u);
            const uint32_t bb = b_base + ((s == 1) ? (uint32_t)(CTA_N * RS)    : 0u);
            #pragma unroll
            for (int ks = 0; ks < 4; ks++) {
                uint32_t a[2][4];
                ldm4(a[0][0], a[0][1], a[0][2], a[0][3], ab + ks * 32);
                ldm4(a[1][0], a[1][1], a[1][2], a[1][3], ab + 16 * RS + ks * 32);
                uint32_t b[NI][2];
                #pragma unroll
                for (int p = 0; p < NI / 2; p++) {
                    uint32_t r0, r1, r2, r3;
                    ldm4(r0, r1, r2, r3, bb + (uint32_t)(p * 16) * RS + ks * 32);
                    b[2 * p][0] = r0; b[2 * p + 1][0] = r1;
                    b[2 * p][1] = r2; b[2 * p + 1][1] = r3;
                }
                #pragma unroll
                for (int mi = 0; mi < 2; mi++)
                    #pragma unroll
                    for (int ni = 0; ni < NI; ni++)
                        mma16816(acc[mi][ni], a[mi], b[ni]);
            }
        }
        __syncthreads();
    }

    // ---- epilogue: bias (+relu), float2 stores ----
    const int g = lane >> 2;
    const int t = lane & 3;
    #pragma unroll
    for (int mi = 0; mi < 2; mi++) {
        const int gm = m0 + warp_m * 32 + mi * 16 + g;
        #pragma unroll
        for (int ni = 0; ni < NI; ni++) {
            const int gn = n0 + warp_n * SPAN + ni * 8 + t * 2;
            const float2 bb = *reinterpret_cast<const float2*>(bias + gn);
            if (gm < M) {
                float2 o = make_float2(acc[mi][ni][0] + bb.x, acc[mi][ni][1] + bb.y);
                if (RELU_OUT) { o.x = fmaxf(o.x, 0.f); o.y = fmaxf(o.y, 0.f); }
                *reinterpret_cast<float2*>(C + (size_t)gm * N + gn) = o;
            }
            if (gm + 8 < M) {
                float2 o = make_float2(acc[mi][ni][2] + bb.x, acc[mi][ni][3] + bb.y);
                if (RELU_OUT) { o.x = fmaxf(o.x, 0.f); o.y = fmaxf(o.y, 0.f); }
                *reinterpret_cast<float2*>(C + (size_t)(gm + 8) * N + gn) = o;
            }
        }
    }
}

// ---------------------------------------------------------------------------
// w1 = edge_feat @ We1 + be1     (E_IN=2)
// ---------------------------------------------------------------------------
__global__ void w1_kernel(const float* __restrict__ ef, const float* __restrict__ We,
                          const float* __restrict__ be, float* __restrict__ w1)
{
    const int idx = blockIdx.x * 256 + threadIdx.x;
    const int e = idx >> 7;
    const int j = idx & 127;
    const float e0 = ef[2 * e];
    const float e1 = ef[2 * e + 1];
    w1[idx] = fmaf(e1, We[128 + j], fmaf(e0, We[j], be[j]));
}

// ---------------------------------------------------------------------------
// per-node inverse norm
// ---------------------------------------------------------------------------
template<int F>
__global__ void norm_kernel(const float* __restrict__ h, float* __restrict__ invn,
                            int n_nodes)
{
    const int n = blockIdx.x * 8 + (threadIdx.x >> 5);
    if (n >= n_nodes) return;
    const int lane = threadIdx.x & 31;
    const float4* h4 = reinterpret_cast<const float4*>(h + (size_t)n * F);
    float ss = 0.f;
    #pragma unroll
    for (int j = 0; j < F / 128; j++) {
        float4 v = h4[lane + j * 32];
        ss += v.x * v.x + v.y * v.y + v.z * v.z + v.w * v.w;
    }
    #pragma unroll
    for (int o = 16; o > 0; o >>= 1) ss += __shfl_xor_sync(0xFFFFFFFFu, ss, o);
    if (lane == 0) invn[n] = 1.f / fmaxf(sqrtf(ss), 1e-12f);
}

// ---------------------------------------------------------------------------
// per-edge message: m[e,:] = cos_e * w[e,:] * h[src[e],:]
// ---------------------------------------------------------------------------
template<int F>
__global__ void msg_kernel(const float* __restrict__ h,
                           const float* w, float* m,
                           const float* __restrict__ invn,
                           const int* __restrict__ src,
                           const int* __restrict__ dst)
{
    const int e    = blockIdx.x * 8 + (threadIdx.x >> 5);
    const int lane = threadIdx.x & 31;
    const int s = src[e];
    const int d = dst[e];
    const float4* hs4 = reinterpret_cast<const float4*>(h + (size_t)s * F);
    const float4* hd4 = reinterpret_cast<const float4*>(h + (size_t)d * F);
    float4 a[F / 128];
    float dot = 0.f;
    #pragma unroll
    for (int j = 0; j < F / 128; j++) {
        a[j] = hs4[lane + j * 32];
        float4 b = hd4[lane + j * 32];
        dot += a[j].x * b.x + a[j].y * b.y + a[j].z * b.z + a[j].w * b.w;
    }
    #pragma unroll
    for (int o = 16; o > 0; o >>= 1) dot += __shfl_xor_sync(0xFFFFFFFFu, dot, o);
    const float c = dot * invn[s] * invn[d];
    const float4* w4 = reinterpret_cast<const float4*>(w + (size_t)e * F);
    float4*       m4 = reinterpret_cast<float4*>(m + (size_t)e * F);
    #pragma unroll
    for (int j = 0; j < F / 128; j++) {
        float4 wv = w4[lane + j * 32];
        float4 o;
        o.x = c * wv.x * a[j].x;
        o.y = c * wv.y * a[j].y;
        o.z = c * wv.z * a[j].z;
        o.w = c * wv.w * a[j].w;
        m4[lane + j * 32] = o;
    }
}

// ---------------------------------------------------------------------------
// degree + scatter-sum
// ---------------------------------------------------------------------------
__global__ void deg_kernel(const int* __restrict__ dst, int* __restrict__ deg)
{
    const int e = blockIdx.x * 256 + threadIdx.x;
    if (e < NE) atomicAdd(&deg[dst[e]], 1);
}

template<int F>
__global__ void scatter_kernel(const float* __restrict__ r,
                               const int* __restrict__ dst,
                               float* hN)
{
    const int e    = blockIdx.x * 8 + (threadIdx.x >> 5);
    const int lane = threadIdx.x & 31;
    const int d = dst[e];
    const float* rr = r + (size_t)e * F;
    float* out = hN + (size_t)d * F;
    #pragma unroll
    for (int j = 0; j < F / 32; j++)
        atomicAdd(out + lane + j * 32, rr[lane + j * 32]);
}

// ---------------------------------------------------------------------------
// cat[n, 0:F] = h; cat[n, F:2F] = hN / max(deg, 1)
// ---------------------------------------------------------------------------
template<int F>
__global__ void cat_kernel(const float* __restrict__ h,
                           const float* __restrict__ hN,
                           const int* __restrict__ deg,
                           float* __restrict__ out, int n_nodes)
{
    const int idx = blockIdx.x * 256 + threadIdx.x;
    if (idx >= n_nodes * 2 * F) return;
    const int n = idx / (2 * F);
    const int k = idx - n * 2 * F;
    float v;
    if (k < F) v = h[(size_t)n * F + k];
    else       v = hN[(size_t)n * F + (k - F)] / fmaxf((float)deg[n], 1.f);
    out[idx] = v;
}

// ---------------------------------------------------------------------------
// launch
// ---------------------------------------------------------------------------
extern "C" void kernel_launch(void* const* d_in, const int* in_sizes, int n_in,
                              void* d_out, int out_size)
{
    (void)in_sizes; (void)n_in; (void)out_size;

    const float* nf   = (const float*)d_in[0];
    const float* ef   = (const float*)d_in[1];
    const int*   src  = (const int*)  d_in[2];
    const int*   dst  = (const int*)  d_in[3];
    const float* We1  = (const float*)d_in[4];
    const float* be1  = (const float*)d_in[5];
    const float* Wr1a = (const float*)d_in[6];
    const float* br1a = (const float*)d_in[7];
    const float* Wr1b = (const float*)d_in[8];
    const float* br1b = (const float*)d_in[9];
    const float* Wl1  = (const float*)d_in[10];
    const float* bl1  = (const float*)d_in[11];
    const float* We2  = (const float*)d_in[12];
    const float* be2  = (const float*)d_in[13];
    const float* Wr2a = (const float*)d_in[14];
    const float* br2a = (const float*)d_in[15];
    const float* Wr2b = (const float*)d_in[16];
    const float* br2b = (const float*)d_in[17];
    const float* Wl2  = (const float*)d_in[18];
    const float* bl2  = (const float*)d_in[19];
    float* out = (float*)d_out;

    float *p_w1, *p_A, *p_B, *p_h1, *p_hN, *p_cat, *p_inv;
    int*   p_deg;
    __nv_bfloat16 *p_bwh, *p_bwl;
    cudaGetSymbolAddress((void**)&p_w1,  g_w1);
    cudaGetSymbolAddress((void**)&p_A,   g_bufA);
    cudaGetSymbolAddress((void**)&p_B,   g_bufB);
    cudaGetSymbolAddress((void**)&p_h1,  g_h1);
    cudaGetSymbolAddress((void**)&p_hN,  g_hN);
    cudaGetSymbolAddress((void**)&p_cat, g_cat);
    cudaGetSymbolAddress((void**)&p_inv, g_inv);
    cudaGetSymbolAddress((void**)&p_deg, g_deg);
    cudaGetSymbolAddress((void**)&p_bwh, g_bwh);
    cudaGetSymbolAddress((void**)&p_bwl, g_bwl);

    // dynamic SMEM: 2*128*144 (A) + 2*CTA_N*144 (B)
    constexpr int SMN128 = 36864 + 128 * 288;   // 73728
    constexpr int SMN32  = 36864 + 32  * 288;   // 46080
    cudaFuncSetAttribute(gemm_mma<128, false, true >, cudaFuncAttributeMaxDynamicSharedMemorySize, SMN128);
    cudaFuncSetAttribute(gemm_mma<128, true,  false>, cudaFuncAttributeMaxDynamicSharedMemorySize, SMN128);
    cudaFuncSetAttribute(gemm_mma<32,  false, false>, cudaFuncAttributeMaxDynamicSharedMemorySize, SMN32);

    // ---- pre-split weights into bf16 hi/lo, transposed [N,K] ----
    conv_w_kernel<<<(128 * 128 + 255) / 256, 256>>>(Wr1a, 128, 128, p_bwh + 0,      p_bwl + 0);
    conv_w_kernel<<<(128 * 128 + 255) / 256, 256>>>(Wr1b, 128, 128, p_bwh + 16384,  p_bwl + 16384);
    conv_w_kernel<<<(128 * 256 + 255) / 256, 256>>>(We2,  128, 256, p_bwh + 32768,  p_bwl + 32768);
    conv_w_kernel<<<(256 * 256 + 255) / 256, 256>>>(Wr2a, 256, 256, p_bwh + 65536,  p_bwl + 65536);
    conv_w_kernel<<<(256 * 256 + 255) / 256, 256>>>(Wr2b, 256, 256, p_bwh + 131072, p_bwl + 131072);
    conv_w_kernel<<<(256 * 256 + 255) / 256, 256>>>(Wl1,  256, 256, p_bwh + 196608, p_bwl + 196608);
    conv_w_kernel<<<(512 * 32  + 255) / 256, 256>>>(Wl2,  512, 32,  p_bwh + 262144, p_bwl + 262144);

    // degree (shared by both layers)
    cudaMemsetAsync(p_deg, 0, NN * sizeof(int));
    deg_kernel<<<(NE + 255) / 256, 256>>>(dst, p_deg);

    const int EG = NE / 128;              // 6250 edge M-tiles
    const int VG = (NN + 127) / 128;      // 391 node M-tiles

    // ======================= layer 1 =======================
    w1_kernel<<<(NE * F1) / 256, 256>>>(ef, We1, be1, p_w1);
    norm_kernel<F1><<<(NN + 7) / 8, 256>>>(nf, p_inv, NN);
    msg_kernel<F1><<<NE / 8, 256>>>(nf, p_w1, p_A, p_inv, src, dst);

    gemm_mma<128, false, true><<<dim3(EG, 1), 256, SMN128>>>(p_A, p_bwh + 0,     p_bwl + 0,     br1a, p_B, NE, 128, 128);
    gemm_mma<128, false, true><<<dim3(EG, 1), 256, SMN128>>>(p_B, p_bwh + 16384, p_bwl + 16384, br1b, p_A, NE, 128, 128);

    cudaMemsetAsync(p_hN, 0, (size_t)NN * F1 * sizeof(float));
    scatter_kernel<F1><<<NE / 8, 256>>>(p_A, dst, p_hN);
    cat_kernel<F1><<<(NN * 2 * F1 + 255) / 256, 256>>>(nf, p_hN, p_deg, p_cat, NN);

    gemm_mma<128, false, true><<<dim3(VG, 2), 256, SMN128>>>(p_cat, p_bwh + 196608, p_bwl + 196608, bl1, p_h1, NN, 256, 256);

    // ======================= layer 2 =======================
    // w2 = relu(w1) @ We2 + be2   (relu fused into A split)
    gemm_mma<128, true, false><<<dim3(EG, 2), 256, SMN128>>>(p_w1, p_bwh + 32768, p_bwl + 32768, be2, p_A, NE, 128, 256);

    norm_kernel<HF><<<(NN + 7) / 8, 256>>>(p_h1, p_inv, NN);
    msg_kernel<HF><<<NE / 8, 256>>>(p_h1, p_A, p_A, p_inv, src, dst);   // in-place

    gemm_mma<128, false, true><<<dim3(EG, 2), 256, SMN128>>>(p_A, p_bwh + 65536,  p_bwl + 65536,  br2a, p_B, NE, 256, 256);
    gemm_mma<128, false, true><<<dim3(EG, 2), 256, SMN128>>>(p_B, p_bwh + 131072, p_bwl + 131072, br2b, p_A, NE, 256, 256);

    cudaMemsetAsync(p_hN, 0, (size_t)NN * HF * sizeof(float));
    scatter_kernel<HF><<<NE / 8, 256>>>(p_A, dst, p_hN);
    cat_kernel<HF><<<(NN * 2 * HF + 255) / 256, 256>>>(p_h1, p_hN, p_deg, p_cat, NN);

    gemm_mma<32, false, false><<<dim3(VG, 1), 256, SMN32>>>(p_cat, p_bwh + 262144, p_bwl + 262144, bl2, out, NN, 512, 32);
}